// round 9
// baseline (speedup 1.0000x reference)
#include <cuda_runtime.h>
#include <cuda_bf16.h>
#include <cstdint>

#define N_NODES 100000
#define N_EDGES 1600000
#define D 64
#define SCAN_BLOCKS 391   // ceil(N_NODES/256)

// ---------------- scratch (static device globals; no allocation) ----------------
__device__ __align__(16) float  g_t[(size_t)N_NODES * D];   // transformed features
__device__ __align__(16) float  g_agg[(size_t)N_NODES * D]; // aggregation output
__device__ __align__(16) int    g_csr[N_EDGES];             // src ids grouped by dst
__device__ __align__(16) int    g_rowptr[N_NODES + 1];
__device__ __align__(16) int    g_woff[N_NODES];            // fill cursors
__device__ __align__(16) int    g_cnt[N_NODES];             // in-degree histogram
__device__ __align__(16) float  g_deg[N_NODES];             // out-degree COUNT (float)
__device__ __align__(16) int    g_bsum[SCAN_BLOCKS];
__device__ __align__(16) int    g_bsum_ex[SCAN_BLOCKS];
__device__ __align__(16) float  g_msum[D];
__device__ int g_is64;

// ---------------- f32x2 helpers -----------------------------------------------------
#define FMA2(d, a, b) \
    asm("fma.rn.f32x2 %0, %1, %2, %0;" : "+l"(d) : "l"(a), "l"(b))

__device__ __forceinline__ uint64_t pack2(float x) {
    uint64_t p;
    asm("mov.b64 %0, {%1, %1};" : "=l"(p) : "f"(x));
    return p;
}
__device__ __forceinline__ float lo32(uint64_t v) {
    return __uint_as_float((unsigned)v);
}
__device__ __forceinline__ float hi32(uint64_t v) {
    return __uint_as_float((unsigned)(v >> 32));
}

// ---------------- helpers ----------------------------------------------------------
__device__ __forceinline__ int idx_at(const void* __restrict__ p, int e, int is64) {
    return is64 ? (int)((const long long*)p)[e] : ((const int*)p)[e];
}

// ---------------- init: zero histograms + msum; parallel dtype detection -----------
__global__ void gcn_init(const void* __restrict__ src) {
    int i = blockIdx.x * blockDim.x + threadIdx.x;
    if (i < N_NODES) { g_cnt[i] = 0; g_deg[i] = 0.0f; }
    if (i < D)       g_msum[i] = 0.0f;

    if (blockIdx.x == 0) {
        __shared__ int ok;
        if (threadIdx.x == 0) ok = 1;
        __syncthreads();
        long long v = ((const long long*)src)[threadIdx.x];
        if (v < 0 || v >= N_NODES) ok = 0;   // benign race, all writers write 0
        __syncthreads();
        if (threadIdx.x == 0) g_is64 = ok;   // JAX int64 silently -> int32
    }
}

// ---------------- prepass: both histograms; 4 edges/thread --------------------------
__global__ void gcn_prep(const void* __restrict__ src, const void* __restrict__ dst) {
    int q = blockIdx.x * blockDim.x + threadIdx.x;
    int e0 = q * 4;
    if (e0 >= N_EDGES) return;
    const int is64 = g_is64;
    int s[4], d[4];
    if (!is64) {
        int4 sv = __ldg((const int4*)src + q);
        int4 dv = __ldg((const int4*)dst + q);
        s[0]=sv.x; s[1]=sv.y; s[2]=sv.z; s[3]=sv.w;
        d[0]=dv.x; d[1]=dv.y; d[2]=dv.z; d[3]=dv.w;
    } else {
        #pragma unroll
        for (int i = 0; i < 4; i++) {
            s[i] = (int)((const long long*)src)[e0 + i];
            d[i] = (int)((const long long*)dst)[e0 + i];
        }
    }
    #pragma unroll
    for (int i = 0; i < 4; i++) {
        int ss = ((unsigned)s[i] < N_NODES) ? s[i] : 0;
        int dd = ((unsigned)d[i] < N_NODES) ? d[i] : 0;
        atomicAdd(&g_deg[ss], 1.0f);
        atomicAdd(&g_cnt[dd], 1);
    }
}

// ---------------- scan stage 1: per-block sums ----------------------------------------
__global__ __launch_bounds__(256) void gcn_scan1() {
    __shared__ int sh[256];
    int i = blockIdx.x * 256 + threadIdx.x;
    sh[threadIdx.x] = (i < N_NODES) ? g_cnt[i] : 0;
    __syncthreads();
    for (int off = 128; off > 0; off >>= 1) {
        if (threadIdx.x < off) sh[threadIdx.x] += sh[threadIdx.x + off];
        __syncthreads();
    }
    if (threadIdx.x == 0) g_bsum[blockIdx.x] = sh[0];
}

// ---------------- scan stage 2: exclusive scan of block sums (1 block) ----------------
__global__ __launch_bounds__(512) void gcn_scan2() {
    __shared__ int sh[512];
    int t = threadIdx.x;
    int v = (t < SCAN_BLOCKS) ? g_bsum[t] : 0;
    sh[t] = v;
    __syncthreads();
    for (int off = 1; off < 512; off <<= 1) {
        int add = (t >= off) ? sh[t - off] : 0;
        __syncthreads();
        sh[t] += add;
        __syncthreads();
    }
    if (t < SCAN_BLOCKS) g_bsum_ex[t] = sh[t] - v;
    if (t == 511) g_rowptr[N_NODES] = sh[511];
}

// ---------------- scan stage 3: local scan + add-back ----------------------------------
__global__ __launch_bounds__(256) void gcn_scan3() {
    __shared__ int sh[256];
    int i = blockIdx.x * 256 + threadIdx.x;
    int t = threadIdx.x;
    int c = (i < N_NODES) ? g_cnt[i] : 0;
    sh[t] = c;
    __syncthreads();
    for (int off = 1; off < 256; off <<= 1) {
        int add = (t >= off) ? sh[t - off] : 0;
        __syncthreads();
        sh[t] += add;
        __syncthreads();
    }
    if (i < N_NODES) {
        int start = g_bsum_ex[blockIdx.x] + sh[t] - c;
        g_rowptr[i] = start;
        g_woff[i]   = start;
    }
}

// ---------------- fill: csr[pos] = src, grouped by dst; 4 edges/thread ----------------
__global__ void gcn_fill(const void* __restrict__ src, const void* __restrict__ dst) {
    int q = blockIdx.x * blockDim.x + threadIdx.x;
    int e0 = q * 4;
    if (e0 >= N_EDGES) return;
    const int is64 = g_is64;
    int s[4], d[4];
    if (!is64) {
        int4 sv = __ldg((const int4*)src + q);
        int4 dv = __ldg((const int4*)dst + q);
        s[0]=sv.x; s[1]=sv.y; s[2]=sv.z; s[3]=sv.w;
        d[0]=dv.x; d[1]=dv.y; d[2]=dv.z; d[3]=dv.w;
    } else {
        #pragma unroll
        for (int i = 0; i < 4; i++) {
            s[i] = (int)((const long long*)src)[e0 + i];
            d[i] = (int)((const long long*)dst)[e0 + i];
        }
    }
    #pragma unroll
    for (int i = 0; i < 4; i++) {
        int ss = ((unsigned)s[i] < N_NODES) ? s[i] : 0;
        int dd = ((unsigned)d[i] < N_NODES) ? d[i] : 0;
        int pos = atomicAdd(&g_woff[dd], 1);
        g_csr[pos] = ss;
    }
}

// ---------------- fused prologue + GEMM with f32x2 packed FMA --------------------------
// g_t[n,:] = prologue(in[n,:]) @ W ; prologue(x) = (relu(x+bias))? / max(deg[n],1)
// 128 threads, 64 rows/block, 2 rows x 16 cols per thread.
// Inner loop per k: 2 LDS.32 + 2 MOV.b64 + 4 LDS.128 + 16 FFMA2 (~24 instrs vs 38 scalar).
__global__ __launch_bounds__(128) void gcn_gemm(
    const float* __restrict__ in_ext, const float* __restrict__ W,
    const float* __restrict__ bias, int use_relu)
{
    __shared__ float Ws[D][D];      // 16 KB
    __shared__ float Xs[64][68];    // 17.4 KB; bank=(4r+k)%32 conflict-free

    const float* in = in_ext ? in_ext : g_agg;
    const int tid = threadIdx.x;
    const int n0  = blockIdx.x * 64;

    {
        const float4* w4 = (const float4*)W;
        float4* ws4 = (float4*)&Ws[0][0];
        #pragma unroll
        for (int i = tid; i < (D * D) / 4; i += 128) ws4[i] = w4[i];
    }
    for (int i = tid; i < 64 * (D / 4); i += 128) {
        int r = i >> 4, q = i & 15;
        int row = n0 + r;
        float4 x = make_float4(0.f, 0.f, 0.f, 0.f);
        if (row < N_NODES) {
            x = __ldg((const float4*)(in + (size_t)row * D) + q);
            if (use_relu) {
                float4 b = __ldg((const float4*)bias + q);
                x.x = fmaxf(x.x + b.x, 0.f); x.y = fmaxf(x.y + b.y, 0.f);
                x.z = fmaxf(x.z + b.z, 0.f); x.w = fmaxf(x.w + b.w, 0.f);
            }
            float di = __fdividef(1.0f, fmaxf(g_deg[row], 1.0f));
            x.x *= di; x.y *= di; x.z *= di; x.w *= di;
        }
        *(float4*)&Xs[r][q * 4] = x;
    }
    __syncthreads();

    const int rb = tid >> 2;          // rows rb, rb+32
    const int c0 = (tid & 3) * 16;    // 16 output cols = 8 f32x2 pairs
    uint64_t acc0[8], acc1[8];
    #pragma unroll
    for (int i = 0; i < 8; i++) { acc0[i] = 0ULL; acc1[i] = 0ULL; }

    #pragma unroll
    for (int k = 0; k < D; k++) {
        uint64_t x0 = pack2(Xs[rb][k]);
        uint64_t x1 = pack2(Xs[rb + 32][k]);
        #pragma unroll
        for (int q = 0; q < 4; q++) {
            // LDS.128 -> two b64 register pairs, already f32x2-shaped
            ulonglong2 w = *(const ulonglong2*)&Ws[k][c0 + q * 4];
            FMA2(acc0[2*q],   x0, w.x);
            FMA2(acc0[2*q+1], x0, w.y);
            FMA2(acc1[2*q],   x1, w.x);
            FMA2(acc1[2*q+1], x1, w.y);
        }
    }

    int row0 = n0 + rb, row1 = n0 + rb + 32;
    if (row0 < N_NODES) {
        float* o = g_t + (size_t)row0 * D + c0;
        #pragma unroll
        for (int q = 0; q < 4; q++)
            *(float4*)(o + q*4) = make_float4(lo32(acc0[2*q]), hi32(acc0[2*q]),
                                              lo32(acc0[2*q+1]), hi32(acc0[2*q+1]));
    }
    if (row1 < N_NODES) {
        float* o = g_t + (size_t)row1 * D + c0;
        #pragma unroll
        for (int q = 0; q < 4; q++)
            *(float4*)(o + q*4) = make_float4(lo32(acc1[2*q]), hi32(acc1[2*q]),
                                              lo32(acc1[2*q+1]), hi32(acc1[2*q+1]));
    }
}

// ---------------- gather core with 8-edge batches (MLP=8) ------------------------------
__device__ __forceinline__ float4 agg_node(int node, int lane) {
    int beg = __ldg(&g_rowptr[node]);
    int end = __ldg(&g_rowptr[node + 1]);
    float4 acc = make_float4(0.f, 0.f, 0.f, 0.f);
    int e = beg;
    for (; e + 8 <= end; e += 8) {
        int s[8];
        #pragma unroll
        for (int i = 0; i < 8; i++) s[i] = __ldg(&g_csr[e + i]);
        float4 v[8];
        #pragma unroll
        for (int i = 0; i < 8; i++)
            v[i] = __ldg((const float4*)(g_t + (size_t)s[i] * D) + lane);
        #pragma unroll
        for (int i = 0; i < 8; i++) {
            acc.x += v[i].x; acc.y += v[i].y; acc.z += v[i].z; acc.w += v[i].w;
        }
    }
    if (e + 4 <= end) {
        int s[4];
        #pragma unroll
        for (int i = 0; i < 4; i++) s[i] = __ldg(&g_csr[e + i]);
        float4 v[4];
        #pragma unroll
        for (int i = 0; i < 4; i++)
            v[i] = __ldg((const float4*)(g_t + (size_t)s[i] * D) + lane);
        #pragma unroll
        for (int i = 0; i < 4; i++) {
            acc.x += v[i].x; acc.y += v[i].y; acc.z += v[i].z; acc.w += v[i].w;
        }
        e += 4;
    }
    for (; e < end; e++) {
        int s = __ldg(&g_csr[e]);
        float4 v = __ldg((const float4*)(g_t + (size_t)s * D) + lane);
        acc.x += v.x; acc.y += v.y; acc.z += v.z; acc.w += v.w;
    }
    return acc;
}

// ---------------- aggregate (layers 0,1): writes g_agg ---------------------------------
__global__ __launch_bounds__(256) void gcn_aggregate()
{
    int node = blockIdx.x * 16 + (threadIdx.x >> 4);
    int lane = threadIdx.x & 15;
    if (node >= N_NODES) return;
    float4 acc = agg_node(node, lane);
    *((float4*)(g_agg + (size_t)node * D) + lane) = acc;
}

// ---------------- aggregate final (layer 2): +b2, write out, fused column sums ---------
__global__ __launch_bounds__(256) void gcn_aggregate_final(
    const float* __restrict__ b2, float* __restrict__ out)
{
    int node = blockIdx.x * 16 + (threadIdx.x >> 4);
    int lane = threadIdx.x & 15;

    float4 acc = agg_node(node, lane);
    float4 bb  = __ldg((const float4*)b2 + lane);
    acc.x += bb.x; acc.y += bb.y; acc.z += bb.z; acc.w += bb.w;
    *((float4*)(out + (size_t)node * D) + lane) = acc;

    __shared__ float4 sdata[256];
    sdata[threadIdx.x] = acc;
    __syncthreads();
    #pragma unroll
    for (int off = 128; off >= 16; off >>= 1) {
        if (threadIdx.x < off) {
            float4 o = sdata[threadIdx.x + off];
            sdata[threadIdx.x].x += o.x; sdata[threadIdx.x].y += o.y;
            sdata[threadIdx.x].z += o.z; sdata[threadIdx.x].w += o.w;
        }
        __syncthreads();
    }
    if (threadIdx.x < 16) {
        float4 s = sdata[threadIdx.x];
        atomicAdd(&g_msum[threadIdx.x * 4 + 0], s.x);
        atomicAdd(&g_msum[threadIdx.x * 4 + 1], s.y);
        atomicAdd(&g_msum[threadIdx.x * 4 + 2], s.z);
        atomicAdd(&g_msum[threadIdx.x * 4 + 3], s.w);
    }
}

__global__ void gcn_mean_write(float* __restrict__ out) {
    int j = threadIdx.x;
    if (j < D) out[(size_t)N_NODES * D + j] = g_msum[j] / (float)N_NODES;
}

// ---------------- launch -----------------------------------------------------------------
extern "C" void kernel_launch(void* const* d_in, const int* in_sizes, int n_in,
                              void* d_out, int out_size)
{
    const float* features = (const float*)d_in[0];
    const void*  src      = d_in[1];
    const void*  dst      = d_in[2];
    const float* W0 = (const float*)d_in[3];
    const float* b0 = (const float*)d_in[4];
    const float* W1 = (const float*)d_in[5];
    const float* b1 = (const float*)d_in[6];
    const float* W2 = (const float*)d_in[7];
    const float* b2 = (const float*)d_in[8];
    float* out = (float*)d_out;

    const int threads      = 256;
    const int blocks_quad  = (N_EDGES / 4 + threads - 1) / threads;  // 1563
    const int blocks_gemm  = (N_NODES + 63) / 64;                    // 1563
    const int blocks_agg   = N_NODES / 16;                           // 6250 (exact)

    // CSR build + degrees; gemm0 hoisted to launch slot 4 for ncu visibility
    gcn_init<<<SCAN_BLOCKS, threads>>>(src);                       // 1
    gcn_prep<<<blocks_quad, threads>>>(src, dst);                  // 2
    gcn_scan1<<<SCAN_BLOCKS, 256>>>();                             // 3
    gcn_gemm<<<blocks_gemm, 128>>>(features, W0, nullptr, 0);      // 4 <- profiled
    gcn_scan2<<<1, 512>>>();                                       // 5
    gcn_scan3<<<SCAN_BLOCKS, 256>>>();                             // 6
    gcn_fill<<<blocks_quad, threads>>>(src, dst);                  // 7

    // layer 0 aggregation
    gcn_aggregate<<<blocks_agg, threads>>>();                      // 8
    // layer 1
    gcn_gemm<<<blocks_gemm, 128>>>(nullptr, W1, b0, 1);            // 9
    gcn_aggregate<<<blocks_agg, threads>>>();                      // 10
    // layer 2 (epilogue fused into aggregate)
    gcn_gemm<<<blocks_gemm, 128>>>(nullptr, W2, b1, 1);            // 11
    gcn_aggregate_final<<<blocks_agg, threads>>>(b2, out);         // 12

    gcn_mean_write<<<1, 64>>>(out);                                // 13
}

// round 10
// speedup vs baseline: 1.2310x; 1.2310x over previous
#include <cuda_runtime.h>
#include <cuda_bf16.h>
#include <cstdint>

#define N_NODES 100000
#define N_EDGES 1600000
#define D 64
#define SCAN_BLOCKS 391   // ceil(N_NODES/256)

// ---------------- scratch (static device globals; no allocation) ----------------
__device__ __align__(16) float  g_t[(size_t)N_NODES * D];   // transformed features
__device__ __align__(16) float  g_agg[(size_t)N_NODES * D]; // aggregation output
__device__ __align__(16) int    g_csr[N_EDGES];             // src ids grouped by dst
__device__ __align__(16) int    g_rowptr[N_NODES + 1];
__device__ __align__(16) int    g_woff[N_NODES];            // fill cursors
__device__ __align__(16) int    g_cnt[N_NODES];             // in-degree histogram
__device__ __align__(16) float  g_deg[N_NODES];             // out-degree COUNT (float)
__device__ __align__(16) int    g_bsum[SCAN_BLOCKS];
__device__ __align__(16) int    g_bsum_ex[SCAN_BLOCKS];
__device__ __align__(16) float  g_msum[D];
__device__ int g_is64;

// ---------------- f32x2 helpers -----------------------------------------------------
#define FMA2(d, a, b) \
    asm("fma.rn.f32x2 %0, %1, %2, %0;" : "+l"(d) : "l"(a), "l"(b))

__device__ __forceinline__ uint64_t pack2(float x) {
    uint64_t p;
    asm("mov.b64 %0, {%1, %1};" : "=l"(p) : "f"(x));
    return p;
}
__device__ __forceinline__ float lo32(uint64_t v) {
    return __uint_as_float((unsigned)v);
}
__device__ __forceinline__ float hi32(uint64_t v) {
    return __uint_as_float((unsigned)(v >> 32));
}

// ---------------- init: zero histograms + msum; parallel dtype detection -----------
__global__ void gcn_init(const void* __restrict__ src) {
    int i = blockIdx.x * blockDim.x + threadIdx.x;
    if (i < N_NODES) { g_cnt[i] = 0; g_deg[i] = 0.0f; }
    if (i < D)       g_msum[i] = 0.0f;

    if (blockIdx.x == 0) {
        __shared__ int ok;
        if (threadIdx.x == 0) ok = 1;
        __syncthreads();
        long long v = ((const long long*)src)[threadIdx.x];
        if (v < 0 || v >= N_NODES) ok = 0;   // benign race, all writers write 0
        __syncthreads();
        if (threadIdx.x == 0) g_is64 = ok;   // JAX int64 silently -> int32
    }
}

// ---------------- prepass: both histograms; 4 edges/thread --------------------------
__global__ void gcn_prep(const void* __restrict__ src, const void* __restrict__ dst) {
    int q = blockIdx.x * blockDim.x + threadIdx.x;
    int e0 = q * 4;
    if (e0 >= N_EDGES) return;
    const int is64 = g_is64;
    int s[4], d[4];
    if (!is64) {
        int4 sv = __ldg((const int4*)src + q);
        int4 dv = __ldg((const int4*)dst + q);
        s[0]=sv.x; s[1]=sv.y; s[2]=sv.z; s[3]=sv.w;
        d[0]=dv.x; d[1]=dv.y; d[2]=dv.z; d[3]=dv.w;
    } else {
        #pragma unroll
        for (int i = 0; i < 4; i++) {
            s[i] = (int)((const long long*)src)[e0 + i];
            d[i] = (int)((const long long*)dst)[e0 + i];
        }
    }
    #pragma unroll
    for (int i = 0; i < 4; i++) {
        int ss = ((unsigned)s[i] < N_NODES) ? s[i] : 0;
        int dd = ((unsigned)d[i] < N_NODES) ? d[i] : 0;
        atomicAdd(&g_deg[ss], 1.0f);
        atomicAdd(&g_cnt[dd], 1);
    }
}

// ---------------- scan stage 1: per-block sums ----------------------------------------
__global__ __launch_bounds__(256) void gcn_scan1() {
    __shared__ int sh[256];
    int i = blockIdx.x * 256 + threadIdx.x;
    sh[threadIdx.x] = (i < N_NODES) ? g_cnt[i] : 0;
    __syncthreads();
    for (int off = 128; off > 0; off >>= 1) {
        if (threadIdx.x < off) sh[threadIdx.x] += sh[threadIdx.x + off];
        __syncthreads();
    }
    if (threadIdx.x == 0) g_bsum[blockIdx.x] = sh[0];
}

// ---------------- scan stage 2: exclusive scan of block sums (1 block) ----------------
__global__ __launch_bounds__(512) void gcn_scan2() {
    __shared__ int sh[512];
    int t = threadIdx.x;
    int v = (t < SCAN_BLOCKS) ? g_bsum[t] : 0;
    sh[t] = v;
    __syncthreads();
    for (int off = 1; off < 512; off <<= 1) {
        int add = (t >= off) ? sh[t - off] : 0;
        __syncthreads();
        sh[t] += add;
        __syncthreads();
    }
    if (t < SCAN_BLOCKS) g_bsum_ex[t] = sh[t] - v;
    if (t == 511) g_rowptr[N_NODES] = sh[511];
}

// ---------------- scan stage 3: local scan + add-back ----------------------------------
__global__ __launch_bounds__(256) void gcn_scan3() {
    __shared__ int sh[256];
    int i = blockIdx.x * 256 + threadIdx.x;
    int t = threadIdx.x;
    int c = (i < N_NODES) ? g_cnt[i] : 0;
    sh[t] = c;
    __syncthreads();
    for (int off = 1; off < 256; off <<= 1) {
        int add = (t >= off) ? sh[t - off] : 0;
        __syncthreads();
        sh[t] += add;
        __syncthreads();
    }
    if (i < N_NODES) {
        int start = g_bsum_ex[blockIdx.x] + sh[t] - c;
        g_rowptr[i] = start;
        g_woff[i]   = start;
    }
}

// ---------------- fill: csr[pos] = src, grouped by dst; 4 edges/thread ----------------
__global__ void gcn_fill(const void* __restrict__ src, const void* __restrict__ dst) {
    int q = blockIdx.x * blockDim.x + threadIdx.x;
    int e0 = q * 4;
    if (e0 >= N_EDGES) return;
    const int is64 = g_is64;
    int s[4], d[4];
    if (!is64) {
        int4 sv = __ldg((const int4*)src + q);
        int4 dv = __ldg((const int4*)dst + q);
        s[0]=sv.x; s[1]=sv.y; s[2]=sv.z; s[3]=sv.w;
        d[0]=dv.x; d[1]=dv.y; d[2]=dv.z; d[3]=dv.w;
    } else {
        #pragma unroll
        for (int i = 0; i < 4; i++) {
            s[i] = (int)((const long long*)src)[e0 + i];
            d[i] = (int)((const long long*)dst)[e0 + i];
        }
    }
    #pragma unroll
    for (int i = 0; i < 4; i++) {
        int ss = ((unsigned)s[i] < N_NODES) ? s[i] : 0;
        int dd = ((unsigned)d[i] < N_NODES) ? d[i] : 0;
        int pos = atomicAdd(&g_woff[dd], 1);
        g_csr[pos] = ss;
    }
}

// ---------------- fused prologue + GEMM, conflict-free W, 4 rows/thread -----------------
// g_t[n,:] = prologue(in[n,:]) @ W ; prologue(x) = (relu(x+bias))? / max(deg[n],1)
// 128 threads, 128 rows/block. Thread owns rows {rb, rb+32, rb+64, rb+96} and
// columns {(tid&3)*4 + 16j + m : j,m in 0..3}. Per (k,j) the 4 quad threads issue
// LDS.128 covering 64 CONTIGUOUS bytes (banks 16j..16j+15) -> conflict-free,
// 8-way broadcast; the old layout had 64B-strided chunks colliding 2-way on banks.
__global__ __launch_bounds__(128) void gcn_gemm(
    const float* __restrict__ in_ext, const float* __restrict__ W,
    const float* __restrict__ bias, int use_relu)
{
    __shared__ float Ws[D][D];        // 16 KB
    __shared__ float Xs[128][68];     // 34.8 KB; Xs bank = (4r+k)%32, conflict-free

    const float* in = in_ext ? in_ext : g_agg;
    const int tid = threadIdx.x;
    const int n0  = blockIdx.x * 128;

    {
        const float4* w4 = (const float4*)W;
        float4* ws4 = (float4*)&Ws[0][0];
        #pragma unroll
        for (int i = tid; i < (D * D) / 4; i += 128) ws4[i] = w4[i];
    }
    for (int i = tid; i < 128 * (D / 4); i += 128) {
        int r = i >> 4, q = i & 15;
        int row = n0 + r;
        float4 x = make_float4(0.f, 0.f, 0.f, 0.f);
        if (row < N_NODES) {
            x = __ldg((const float4*)(in + (size_t)row * D) + q);
            if (use_relu) {
                float4 b = __ldg((const float4*)bias + q);
                x.x = fmaxf(x.x + b.x, 0.f); x.y = fmaxf(x.y + b.y, 0.f);
                x.z = fmaxf(x.z + b.z, 0.f); x.w = fmaxf(x.w + b.w, 0.f);
            }
            float di = __fdividef(1.0f, fmaxf(g_deg[row], 1.0f));
            x.x *= di; x.y *= di; x.z *= di; x.w *= di;
        }
        *(float4*)&Xs[r][q * 4] = x;
    }
    __syncthreads();

    const int rb = tid >> 2;          // rows rb, rb+32, rb+64, rb+96
    const int cq = (tid & 3) * 4;     // column chunk base within each 16-col group
    uint64_t acc0[8], acc1[8], acc2[8], acc3[8];
    #pragma unroll
    for (int i = 0; i < 8; i++) { acc0[i]=0ULL; acc1[i]=0ULL; acc2[i]=0ULL; acc3[i]=0ULL; }

    #pragma unroll 8
    for (int k = 0; k < D; k++) {
        uint64_t x0 = pack2(Xs[rb][k]);
        uint64_t x1 = pack2(Xs[rb + 32][k]);
        uint64_t x2 = pack2(Xs[rb + 64][k]);
        uint64_t x3 = pack2(Xs[rb + 96][k]);
        #pragma unroll
        for (int j = 0; j < 4; j++) {
            ulonglong2 w = *(const ulonglong2*)&Ws[k][j * 16 + cq];
            FMA2(acc0[2*j],   x0, w.x); FMA2(acc0[2*j+1], x0, w.y);
            FMA2(acc1[2*j],   x1, w.x); FMA2(acc1[2*j+1], x1, w.y);
            FMA2(acc2[2*j],   x2, w.x); FMA2(acc2[2*j+1], x2, w.y);
            FMA2(acc3[2*j],   x3, w.x); FMA2(acc3[2*j+1], x3, w.y);
        }
    }

    #pragma unroll
    for (int rr = 0; rr < 4; rr++) {
        int row = n0 + rb + rr * 32;
        if (row >= N_NODES) break;
        const uint64_t* acc = (rr == 0) ? acc0 : (rr == 1) ? acc1 : (rr == 2) ? acc2 : acc3;
        float* o = g_t + (size_t)row * D;
        #pragma unroll
        for (int j = 0; j < 4; j++)
            *(float4*)(o + j * 16 + cq) = make_float4(
                lo32(acc[2*j]),   hi32(acc[2*j]),
                lo32(acc[2*j+1]), hi32(acc[2*j+1]));
    }
}

// ---------------- gather core with 8-edge batches (MLP=8) ------------------------------
__device__ __forceinline__ float4 agg_node(int node, int lane) {
    int beg = __ldg(&g_rowptr[node]);
    int end = __ldg(&g_rowptr[node + 1]);
    float4 acc = make_float4(0.f, 0.f, 0.f, 0.f);
    int e = beg;
    for (; e + 8 <= end; e += 8) {
        int s[8];
        #pragma unroll
        for (int i = 0; i < 8; i++) s[i] = __ldg(&g_csr[e + i]);
        float4 v[8];
        #pragma unroll
        for (int i = 0; i < 8; i++)
            v[i] = __ldg((const float4*)(g_t + (size_t)s[i] * D) + lane);
        #pragma unroll
        for (int i = 0; i < 8; i++) {
            acc.x += v[i].x; acc.y += v[i].y; acc.z += v[i].z; acc.w += v[i].w;
        }
    }
    if (e + 4 <= end) {
        int s[4];
        #pragma unroll
        for (int i = 0; i < 4; i++) s[i] = __ldg(&g_csr[e + i]);
        float4 v[4];
        #pragma unroll
        for (int i = 0; i < 4; i++)
            v[i] = __ldg((const float4*)(g_t + (size_t)s[i] * D) + lane);
        #pragma unroll
        for (int i = 0; i < 4; i++) {
            acc.x += v[i].x; acc.y += v[i].y; acc.z += v[i].z; acc.w += v[i].w;
        }
        e += 4;
    }
    for (; e < end; e++) {
        int s = __ldg(&g_csr[e]);
        float4 v = __ldg((const float4*)(g_t + (size_t)s * D) + lane);
        acc.x += v.x; acc.y += v.y; acc.z += v.z; acc.w += v.w;
    }
    return acc;
}

// ---------------- aggregate (layers 0,1): writes g_agg ---------------------------------
__global__ __launch_bounds__(256) void gcn_aggregate()
{
    int node = blockIdx.x * 16 + (threadIdx.x >> 4);
    int lane = threadIdx.x & 15;
    if (node >= N_NODES) return;
    float4 acc = agg_node(node, lane);
    *((float4*)(g_agg + (size_t)node * D) + lane) = acc;
}

// ---------------- aggregate final (layer 2): +b2, write out, fused column sums ---------
__global__ __launch_bounds__(256) void gcn_aggregate_final(
    const float* __restrict__ b2, float* __restrict__ out)
{
    int node = blockIdx.x * 16 + (threadIdx.x >> 4);
    int lane = threadIdx.x & 15;

    float4 acc = agg_node(node, lane);
    float4 bb  = __ldg((const float4*)b2 + lane);
    acc.x += bb.x; acc.y += bb.y; acc.z += bb.z; acc.w += bb.w;
    *((float4*)(out + (size_t)node * D) + lane) = acc;

    __shared__ float4 sdata[256];
    sdata[threadIdx.x] = acc;
    __syncthreads();
    #pragma unroll
    for (int off = 128; off >= 16; off >>= 1) {
        if (threadIdx.x < off) {
            float4 o = sdata[threadIdx.x + off];
            sdata[threadIdx.x].x += o.x; sdata[threadIdx.x].y += o.y;
            sdata[threadIdx.x].z += o.z; sdata[threadIdx.x].w += o.w;
        }
        __syncthreads();
    }
    if (threadIdx.x < 16) {
        float4 s = sdata[threadIdx.x];
        atomicAdd(&g_msum[threadIdx.x * 4 + 0], s.x);
        atomicAdd(&g_msum[threadIdx.x * 4 + 1], s.y);
        atomicAdd(&g_msum[threadIdx.x * 4 + 2], s.z);
        atomicAdd(&g_msum[threadIdx.x * 4 + 3], s.w);
    }
}

__global__ void gcn_mean_write(float* __restrict__ out) {
    int j = threadIdx.x;
    if (j < D) out[(size_t)N_NODES * D + j] = g_msum[j] / (float)N_NODES;
}

// ---------------- launch -----------------------------------------------------------------
extern "C" void kernel_launch(void* const* d_in, const int* in_sizes, int n_in,
                              void* d_out, int out_size)
{
    const float* features = (const float*)d_in[0];
    const void*  src      = d_in[1];
    const void*  dst      = d_in[2];
    const float* W0 = (const float*)d_in[3];
    const float* b0 = (const float*)d_in[4];
    const float* W1 = (const float*)d_in[5];
    const float* b1 = (const float*)d_in[6];
    const float* W2 = (const float*)d_in[7];
    const float* b2 = (const float*)d_in[8];
    float* out = (float*)d_out;

    const int threads      = 256;
    const int blocks_quad  = (N_EDGES / 4 + threads - 1) / threads;  // 1563
    const int blocks_gemm  = (N_NODES + 127) / 128;                  // 782
    const int blocks_agg   = N_NODES / 16;                           // 6250 (exact)

    // CSR build + degrees; gemm0 stays in launch slot 4 for ncu visibility
    gcn_init<<<SCAN_BLOCKS, threads>>>(src);                       // 1
    gcn_prep<<<blocks_quad, threads>>>(src, dst);                  // 2
    gcn_scan1<<<SCAN_BLOCKS, 256>>>();                             // 3
    gcn_gemm<<<blocks_gemm, 128>>>(features, W0, nullptr, 0);      // 4 <- profiled
    gcn_scan2<<<1, 512>>>();                                       // 5
    gcn_scan3<<<SCAN_BLOCKS, 256>>>();                             // 6
    gcn_fill<<<blocks_quad, threads>>>(src, dst);                  // 7

    // layer 0 aggregation
    gcn_aggregate<<<blocks_agg, threads>>>();                      // 8
    // layer 1
    gcn_gemm<<<blocks_gemm, 128>>>(nullptr, W1, b0, 1);            // 9
    gcn_aggregate<<<blocks_agg, threads>>>();                      // 10
    // layer 2 (epilogue fused into aggregate)
    gcn_gemm<<<blocks_gemm, 128>>>(nullptr, W2, b1, 1);            // 11
    gcn_aggregate_final<<<blocks_agg, threads>>>(b2, out);         // 12

    gcn_mean_write<<<1, 64>>>(out);                                // 13
}